// round 1
// baseline (speedup 1.0000x reference)
#include <cuda_runtime.h>
#include <cuda_bf16.h>
#include <math.h>

#define BATCH 2
#define SEQ   2048
#define DIM   1024
#define NHEAD 16
#define HD    64
#define MROWS (BATCH * SEQ)   // 4096

// ---------------- scratch (device globals; no runtime allocation) ----------
__device__ float g_q[MROWS * DIM];
__device__ float g_k[MROWS * DIM];
__device__ float g_v[MROWS * DIM];
__device__ float g_ctx[MROWS * DIM];

// ---------------- SGEMM + bias: C[M,N] = A[M,K] @ B[K,N] + bias[N] ---------
#define BM 128
#define BN 128
#define BK 16
#define TM 8
#define TN 8
// 256 threads

__global__ __launch_bounds__(256) void sgemm_bias_kernel(
    const float* __restrict__ A, const float* __restrict__ B,
    const float* __restrict__ bias, float* __restrict__ C,
    int M, int N, int K)
{
    __shared__ float As[BK][BM];   // transposed A tile
    __shared__ float Bs[BK][BN];

    const int tid = threadIdx.x;
    const int tr  = tid >> 4;      // 0..15 (row group)
    const int tc  = tid & 15;      // 0..15 (col group)
    const int blockRow = blockIdx.y * BM;
    const int blockCol = blockIdx.x * BN;

    // A tile load mapping: 128 rows x 16 k; thread handles rows a_r, a_r+64
    const int a_r = tid >> 2;          // 0..63
    const int a_c = (tid & 3) << 2;    // 0,4,8,12
    // B tile load mapping: 16 rows x 128 n; thread handles rows b_r, b_r+8
    const int b_r = tid >> 5;          // 0..7
    const int b_c = (tid & 31) << 2;   // 0..124

    float acc[TM][TN];
    #pragma unroll
    for (int i = 0; i < TM; i++)
        #pragma unroll
        for (int j = 0; j < TN; j++) acc[i][j] = 0.f;

    for (int k0 = 0; k0 < K; k0 += BK) {
        #pragma unroll
        for (int s = 0; s < 2; s++) {
            int r = a_r + s * 64;
            float4 v = *(const float4*)(A + (size_t)(blockRow + r) * K + k0 + a_c);
            As[a_c + 0][r] = v.x;
            As[a_c + 1][r] = v.y;
            As[a_c + 2][r] = v.z;
            As[a_c + 3][r] = v.w;
        }
        #pragma unroll
        for (int s = 0; s < 2; s++) {
            int r = b_r + s * 8;
            *(float4*)(&Bs[r][b_c]) =
                *(const float4*)(B + (size_t)(k0 + r) * N + blockCol + b_c);
        }
        __syncthreads();

        #pragma unroll
        for (int k = 0; k < BK; k++) {
            float rm[TM], rn[TN];
            #pragma unroll
            for (int i = 0; i < TM; i += 4)
                *(float4*)(&rm[i]) = *(const float4*)(&As[k][tr * TM + i]);
            #pragma unroll
            for (int j = 0; j < TN; j += 4)
                *(float4*)(&rn[j]) = *(const float4*)(&Bs[k][tc * TN + j]);
            #pragma unroll
            for (int i = 0; i < TM; i++)
                #pragma unroll
                for (int j = 0; j < TN; j++)
                    acc[i][j] += rm[i] * rn[j];
        }
        __syncthreads();
    }

    #pragma unroll
    for (int i = 0; i < TM; i++) {
        int row = blockRow + tr * TM + i;
        #pragma unroll
        for (int j = 0; j < TN; j += 4) {
            int col = blockCol + tc * TN + j;
            float4 bv = *(const float4*)(bias + col);
            float4 o;
            o.x = acc[i][j + 0] + bv.x;
            o.y = acc[i][j + 1] + bv.y;
            o.z = acc[i][j + 2] + bv.z;
            o.w = acc[i][j + 3] + bv.w;
            *(float4*)(C + (size_t)row * N + col) = o;
        }
    }
}

// ---------------- Flash attention (fp32, causal, softmax-one) --------------
// grid: (SEQ/64, BATCH*NHEAD), block 128 threads.
// Br=64 q rows, Bc=64 keys, hd=64. Thread (ty=tid/16, tx=tid%16):
// owns rows ty*8..+7, cols 4*tx..+3.
#define ATT_SMEM_FLOATS (64*64 /*Qs*/ + 64*65 /*Ks*/ + 64*64 /*Vs*/ + 64*64 /*Ps*/)

__global__ __launch_bounds__(128) void flash_attn_kernel(
    const float* __restrict__ Q, const float* __restrict__ K,
    const float* __restrict__ V, float* __restrict__ O)
{
    const int qt  = blockIdx.x;            // q tile 0..31
    const int bh  = blockIdx.y;            // 0..31
    const int b   = bh >> 4;
    const int h   = bh & 15;
    const int tid = threadIdx.x;
    const int tx  = tid & 15;
    const int ty  = tid >> 4;              // 0..7

    extern __shared__ float sm[];
    float* Qs = sm;                        // [64][64]
    float* Ks = Qs + 64 * 64;              // [64][65] padded
    float* Vs = Ks + 64 * 65;              // [64][64]
    float* Ps = Vs + 64 * 64;              // [64][64]

    const int qbase = qt * 64;
    const size_t head_off = ((size_t)b * SEQ) * DIM + (size_t)h * HD;

    // load + prescale Q tile (1/sqrt(64) = 0.125)
    #pragma unroll
    for (int s = 0; s < 8; s++) {
        int f  = tid + s * 128;            // 0..1023 float4 slots
        int r  = f >> 4;
        int c4 = (f & 15) << 2;
        float4 v = *(const float4*)(Q + head_off + (size_t)(qbase + r) * DIM + c4);
        v.x *= 0.125f; v.y *= 0.125f; v.z *= 0.125f; v.w *= 0.125f;
        *(float4*)(Qs + r * 64 + c4) = v;
    }

    float o[8][4];
    float m[8], l[8];
    #pragma unroll
    for (int i = 0; i < 8; i++) {
        m[i] = -INFINITY; l[i] = 0.f;
        #pragma unroll
        for (int j = 0; j < 4; j++) o[i][j] = 0.f;
    }

    for (int kt = 0; kt <= qt; kt++) {
        const int kbase = kt * 64;
        __syncthreads();   // previous iteration consumers done (also covers Qs on iter 0)

        #pragma unroll
        for (int s = 0; s < 8; s++) {
            int f  = tid + s * 128;
            int r  = f >> 4;
            int c4 = (f & 15) << 2;
            float4 kv = *(const float4*)(K + head_off + (size_t)(kbase + r) * DIM + c4);
            Ks[r * 65 + c4 + 0] = kv.x;
            Ks[r * 65 + c4 + 1] = kv.y;
            Ks[r * 65 + c4 + 2] = kv.z;
            Ks[r * 65 + c4 + 3] = kv.w;
            float4 vv = *(const float4*)(V + head_off + (size_t)(kbase + r) * DIM + c4);
            *(float4*)(Vs + r * 64 + c4) = vv;
        }
        __syncthreads();

        // S = Qs @ Ks^T  (8x4 per thread)
        float s_[8][4];
        #pragma unroll
        for (int i = 0; i < 8; i++)
            #pragma unroll
            for (int j = 0; j < 4; j++) s_[i][j] = 0.f;

        #pragma unroll 2
        for (int d = 0; d < 64; d++) {
            float kreg[4];
            #pragma unroll
            for (int j = 0; j < 4; j++) kreg[j] = Ks[(4 * tx + j) * 65 + d];
            #pragma unroll
            for (int i = 0; i < 8; i++) {
                float qv = Qs[(ty * 8 + i) * 64 + d];
                #pragma unroll
                for (int j = 0; j < 4; j++) s_[i][j] += qv * kreg[j];
            }
        }

        // causal mask — only the diagonal tile is partially masked
        if (kt == qt) {
            #pragma unroll
            for (int i = 0; i < 8; i++)
                #pragma unroll
                for (int j = 0; j < 4; j++)
                    if (4 * tx + j > ty * 8 + i) s_[i][j] = -INFINITY;
        }

        // online softmax-one update; write P tile
        #pragma unroll
        for (int i = 0; i < 8; i++) {
            float rm = fmaxf(fmaxf(s_[i][0], s_[i][1]), fmaxf(s_[i][2], s_[i][3]));
            #pragma unroll
            for (int off = 8; off > 0; off >>= 1)
                rm = fmaxf(rm, __shfl_xor_sync(0xffffffffu, rm, off));
            float mnew = fmaxf(m[i], rm);
            float ps = 0.f;
            #pragma unroll
            for (int j = 0; j < 4; j++) {
                float p = __expf(s_[i][j] - mnew);
                Ps[(ty * 8 + i) * 64 + 4 * tx + j] = p;
                ps += p;
            }
            #pragma unroll
            for (int off = 8; off > 0; off >>= 1)
                ps += __shfl_xor_sync(0xffffffffu, ps, off);
            float corr = __expf(m[i] - mnew);   // 0 when m was -inf
            l[i] = l[i] * corr + ps;
            m[i] = mnew;
            #pragma unroll
            for (int j = 0; j < 4; j++) o[i][j] *= corr;
        }
        __syncthreads();   // P visible to all

        // O += P @ V
        #pragma unroll 2
        for (int kk = 0; kk < 64; kk++) {
            float4 rv = *(const float4*)(Vs + kk * 64 + 4 * tx);
            #pragma unroll
            for (int i = 0; i < 8; i++) {
                float pv = Ps[(ty * 8 + i) * 64 + kk];
                o[i][0] += pv * rv.x;
                o[i][1] += pv * rv.y;
                o[i][2] += pv * rv.z;
                o[i][3] += pv * rv.w;
            }
        }
    }

    // epilogue: divide by (1 + l) — softmax-one denominator
    #pragma unroll
    for (int i = 0; i < 8; i++) {
        float inv = 1.f / (1.f + l[i]);
        float4 w;
        w.x = o[i][0] * inv;
        w.y = o[i][1] * inv;
        w.z = o[i][2] * inv;
        w.w = o[i][3] * inv;
        *(float4*)(O + head_off + (size_t)(qbase + ty * 8 + i) * DIM + 4 * tx) = w;
    }
}

// ---------------- launcher -------------------------------------------------
extern "C" void kernel_launch(void* const* d_in, const int* in_sizes, int n_in,
                              void* d_out, int out_size)
{
    const float* x  = (const float*)d_in[0];
    const float* Wq = (const float*)d_in[1];
    const float* bq = (const float*)d_in[2];
    const float* Wk = (const float*)d_in[3];
    const float* bk = (const float*)d_in[4];
    const float* Wv = (const float*)d_in[5];
    const float* bv = (const float*)d_in[6];
    const float* Wo = (const float*)d_in[7];
    const float* bo = (const float*)d_in[8];
    float* out = (float*)d_out;

    float *q, *k, *v, *ctx;
    cudaGetSymbolAddress((void**)&q,   g_q);
    cudaGetSymbolAddress((void**)&k,   g_k);
    cudaGetSymbolAddress((void**)&v,   g_v);
    cudaGetSymbolAddress((void**)&ctx, g_ctx);

    const int smem = ATT_SMEM_FLOATS * (int)sizeof(float);
    cudaFuncSetAttribute(flash_attn_kernel,
                         cudaFuncAttributeMaxDynamicSharedMemorySize, smem);

    dim3 gemmGrid(DIM / BN, MROWS / BM);    // (8, 32)
    sgemm_bias_kernel<<<gemmGrid, 256>>>(x, Wq, bq, q, MROWS, DIM, DIM);
    sgemm_bias_kernel<<<gemmGrid, 256>>>(x, Wk, bk, k, MROWS, DIM, DIM);
    sgemm_bias_kernel<<<gemmGrid, 256>>>(x, Wv, bv, v, MROWS, DIM, DIM);

    dim3 attnGrid(SEQ / 64, BATCH * NHEAD); // (32, 32)
    flash_attn_kernel<<<attnGrid, 128, smem>>>(q, k, v, ctx);

    sgemm_bias_kernel<<<gemmGrid, 256>>>(ctx, Wo, bo, out, MROWS, DIM, DIM);
}